// round 10
// baseline (speedup 1.0000x reference)
#include <cuda_runtime.h>
#include <cuda_bf16.h>
#include <stdint.h>
#include <cstdint>
#include <math.h>

typedef unsigned int u32;

#define D_DIM 512
#define NB 4096
#define NK 16384
#define BETA 5.5f
#define ALPHA 0.5f
#define QT 64
#define TKEY 32
#define KSPLIT 4
#define NITER (NK / KSPLIT / TKEY)   // 128

// scratch
__device__ __nv_bfloat16 g_qh[(size_t)NB * D_DIM];     // normalized queries bf16 (4 MB)
__device__ __nv_bfloat16 g_ckh[(size_t)NK * D_DIM];    // normalized keys bf16   (16 MB)
__device__ float g_part[(size_t)KSPLIT * NB * D_DIM];  // split-K partials       (32 MB)

// ---------------------------------------------------------------------------
// PTX helpers (only instructions proven to compile for this target)
// ---------------------------------------------------------------------------
__device__ __forceinline__ void cp16(u32 saddr, const void* g) {
    asm volatile("cp.async.cg.shared.global [%0], [%1], 16;\n" :: "r"(saddr), "l"(g));
}
__device__ __forceinline__ void cp_commit() { asm volatile("cp.async.commit_group;\n"); }
__device__ __forceinline__ void cp_wait_1() { asm volatile("cp.async.wait_group 1;\n"); }
__device__ __forceinline__ void cp_wait_0() { asm volatile("cp.async.wait_group 0;\n"); }

__device__ __forceinline__ void ldsm_x4(u32* r, u32 addr) {
    asm volatile("ldmatrix.sync.aligned.m8n8.x4.shared.b16 {%0,%1,%2,%3}, [%4];\n"
        : "=r"(r[0]), "=r"(r[1]), "=r"(r[2]), "=r"(r[3]) : "r"(addr));
}
__device__ __forceinline__ void ldsm_x4_t(u32* r, u32 addr) {
    asm volatile("ldmatrix.sync.aligned.m8n8.x4.trans.shared.b16 {%0,%1,%2,%3}, [%4];\n"
        : "=r"(r[0]), "=r"(r[1]), "=r"(r[2]), "=r"(r[3]) : "r"(addr));
}
__device__ __forceinline__ void mma16816(float* c, const u32* a, u32 b0, u32 b1) {
    asm volatile(
        "mma.sync.aligned.m16n8k16.row.col.f32.bf16.bf16.f32 "
        "{%0,%1,%2,%3}, {%4,%5,%6,%7}, {%8,%9}, {%0,%1,%2,%3};\n"
        : "+f"(c[0]), "+f"(c[1]), "+f"(c[2]), "+f"(c[3])
        : "r"(a[0]), "r"(a[1]), "r"(a[2]), "r"(a[3]), "r"(b0), "r"(b1));
}

// Swizzled offset for 1024-byte rows (q and ck tiles): r = row, c = 16B chunk
// index (0..63). XOR low-3 chunk bits with low-3 row bits -> conflict-free
// ldmatrix phases (8 consecutive rows, same chunk -> 8 distinct banks).
__device__ __forceinline__ u32 qoff(int r, int c) {
    return (u32)(r * 1024 + (((c & ~7) + ((c ^ r) & 7)) << 4));
}

// smem map (dynamic, 1024-aligned)
#define SM_Q   0
#define SM_CK  65536
#define CK_STG 32768
#define SM_S   163840
#define S_STG  5120
#define SMEM_TOTAL 174080

// ---------------------------------------------------------------------------
// Row L2-normalization -> bf16. One warp per 512-float row.
// ---------------------------------------------------------------------------
__global__ void __launch_bounds__(256) norm_rows(const float* __restrict__ src,
                                                 int rows, int dst_sel) {
    int w = (blockIdx.x * blockDim.x + threadIdx.x) >> 5;
    if (w >= rows) return;
    int lane = threadIdx.x & 31;
    __nv_bfloat16* dst = dst_sel ? g_ckh : g_qh;

    const float4* s = (const float4*)(src + (size_t)w * D_DIM);
    float4 v[4];
    float ss = 0.f;
#pragma unroll
    for (int i = 0; i < 4; i++) {
        v[i] = s[lane + 32 * i];
        ss += v[i].x * v[i].x + v[i].y * v[i].y + v[i].z * v[i].z + v[i].w * v[i].w;
    }
#pragma unroll
    for (int o = 16; o; o >>= 1) {
        ss += __shfl_xor_sync(0xffffffffu, ss, o);
    }
    float inv = 1.0f / fmaxf(sqrtf(ss), 1e-12f);

    uint2* d = (uint2*)(dst + (size_t)w * D_DIM);
#pragma unroll
    for (int i = 0; i < 4; i++) {
        __nv_bfloat162 lo = __floats2bfloat162_rn(v[i].x * inv, v[i].y * inv);
        __nv_bfloat162 hi = __floats2bfloat162_rn(v[i].z * inv, v[i].w * inv);
        uint2 u;
        u.x = *(u32*)&lo;
        u.y = *(u32*)&hi;
        d[lane + 32 * i] = u;
    }
}

// ---------------------------------------------------------------------------
// Tile loaders (cp.async, one commit group each)
// ---------------------------------------------------------------------------
__device__ __forceinline__ void load_ck_tile(u32 dst, const __nv_bfloat16* gsrc, int tid) {
#pragma unroll
    for (int i = 0; i < 8; i++) {
        int chunk = tid + i * 256;      // 0..2047: 32 rows x 64 chunks
        int r = chunk >> 6;
        int c = chunk & 63;
        cp16(dst + qoff(r, c), (const char*)gsrc + ((size_t)r * D_DIM + c * 8) * 2);
    }
    cp_commit();
}

__device__ __forceinline__ void load_q_tile(u32 dst, const __nv_bfloat16* gsrc, int tid) {
#pragma unroll
    for (int i = 0; i < 16; i++) {
        int chunk = tid + i * 256;      // 0..4095: 64 rows x 64 chunks
        int r = chunk >> 6;
        int c = chunk & 63;
        cp16(dst + qoff(r, c), (const char*)gsrc + ((size_t)r * D_DIM + c * 8) * 2);
    }
    cp_commit();
}

// ---------------------------------------------------------------------------
// Fused kernel. Grid (NB/64, KSPLIT). 256 threads = 8 warps.
// Warp (wr, wc): wr = m-group (16 q rows), wc = n-half (GEMM1 S cols) and
// d-half (GEMM2 output cols).
// Per key tile t: S = q . ck^T (HMMA) -> exp -> bf16 S smem -> retrieved += S . ck.
// ---------------------------------------------------------------------------
__global__ void __launch_bounds__(256, 1) fused_kernel() {
    extern __shared__ __align__(1024) char sm[];
    const u32 smb = (u32)__cvta_generic_to_shared(sm);
    const int tid = threadIdx.x;
    const int lane = tid & 31;
    const int warp = tid >> 5;
    const int wr = warp >> 1;
    const int wc = warp & 1;
    const int m0 = wr * 16;
    const int n0 = wc * 16;
    const int q0 = blockIdx.x * QT;
    const int z = blockIdx.y;
    const int key0 = z * (NK / KSPLIT);

    float acc2[32][4] = {};   // GEMM2 accum: warp covers 16 q rows x 256 d cols

    load_q_tile(smb + SM_Q, g_qh + (size_t)q0 * D_DIM, tid);
    load_ck_tile(smb + SM_CK + 0 * CK_STG, g_ckh + (size_t)key0 * D_DIM, tid);
    load_ck_tile(smb + SM_CK + 1 * CK_STG, g_ckh + (size_t)(key0 + TKEY) * D_DIM, tid);

    for (int t = 0; t < NITER; t++) {
        if (t + 2 < NITER) {
            cp_wait_1();        // ck(t) landed (FIFO group completion)
        } else {
            cp_wait_0();
        }
        __syncthreads();        // all warps done with GEMM2(t-1); ck(t) visible
        if (t + 2 < NITER) {
            load_ck_tile(smb + SM_CK + ((t + 2) % 3) * CK_STG,
                         g_ckh + (size_t)(key0 + (t + 2) * TKEY) * D_DIM, tid);
        }

        u32 ckb = smb + SM_CK + (t % 3) * CK_STG;

        // ---- GEMM1: S[16x16 per warp] over k = 512 ----
        float accS[2][4] = {};
#pragma unroll
        for (int s = 0; s < 32; s++) {
            u32 a[4];
            u32 b[4];
            ldsm_x4(a, smb + SM_Q + qoff(m0 + (lane & 15), s * 2 + (lane >> 4)));
            ldsm_x4(b, ckb + qoff(n0 + (lane & 15), s * 2 + (lane >> 4)));
            mma16816(accS[0], a, b[0], b[2]);   // key cols n0+0..7
            mma16816(accS[1], a, b[1], b[3]);   // key cols n0+8..15
        }

        // ---- exp -> bf16 S smem (80B rows, double-buffered) ----
        u32 sb = smb + SM_S + (t & 1) * S_STG;
        {
            int r0 = m0 + (lane >> 2);
            int cb = n0 + (lane & 3) * 2;
#pragma unroll
            for (int j = 0; j < 2; j++) {
                float e0 = __expf(fmaf(BETA, accS[j][0], -BETA));
                float e1 = __expf(fmaf(BETA, accS[j][1], -BETA));
                float e2 = __expf(fmaf(BETA, accS[j][2], -BETA));
                float e3 = __expf(fmaf(BETA, accS[j][3], -BETA));
                u32 p01, p23;
                asm("cvt.rn.bf16x2.f32 %0, %1, %2;" : "=r"(p01) : "f"(e1), "f"(e0));
                asm("cvt.rn.bf16x2.f32 %0, %1, %2;" : "=r"(p23) : "f"(e3), "f"(e2));
                u32 colb = (u32)((cb + j * 8) * 2);
                asm volatile("st.shared.b32 [%0], %1;"
                             :: "r"(sb + (u32)(r0 * 80) + colb), "r"(p01));
                asm volatile("st.shared.b32 [%0], %1;"
                             :: "r"(sb + (u32)((r0 + 8) * 80) + colb), "r"(p23));
            }
        }
        __syncthreads();        // S complete for all warps

        // ---- GEMM2: retrieved[16 x 256(wc half)] += S[16x32] . ck[32 x d] ----
        u32 aS[2][4];
        ldsm_x4(aS[0], sb + (u32)((m0 + (lane & 15)) * 80 + (0 + (lane >> 4)) * 16));
        ldsm_x4(aS[1], sb + (u32)((m0 + (lane & 15)) * 80 + (2 + (lane >> 4)) * 16));
#pragma unroll
        for (int c = 0; c < 16; c++) {
#pragma unroll
            for (int ks = 0; ks < 2; ks++) {
                u32 b[4];
                ldsm_x4_t(b, ckb + qoff(ks * 16 + (lane & 15),
                                        wc * 32 + c * 2 + (lane >> 4)));
                mma16816(acc2[c * 2 + 0], aS[ks], b[0], b[1]);  // d cols c*16+0..7
                mma16816(acc2[c * 2 + 1], aS[ks], b[2], b[3]);  // d cols c*16+8..15
            }
        }
    }

    // ---- epilogue: fp32 partials ----
    {
        float* pb = g_part + ((size_t)z * NB + q0 + m0 + (lane >> 2)) * D_DIM;
#pragma unroll
        for (int c = 0; c < 16; c++) {
#pragma unroll
            for (int jj = 0; jj < 2; jj++) {
                int col = wc * 256 + c * 16 + jj * 8 + (lane & 3) * 2;
                float2 v0;
                v0.x = acc2[c * 2 + jj][0];
                v0.y = acc2[c * 2 + jj][1];
                float2 v1;
                v1.x = acc2[c * 2 + jj][2];
                v1.y = acc2[c * 2 + jj][3];
                *(float2*)(pb + col) = v0;
                *(float2*)(pb + 8 * D_DIM + col) = v1;
            }
        }
    }
}

// ---------------------------------------------------------------------------
// Reduce: out = q + ALPHA * sum_z part[z]
// ---------------------------------------------------------------------------
__global__ void __launch_bounds__(256) reduce_kernel(const float* __restrict__ Qorig,
                                                     float* __restrict__ Out) {
    size_t i = ((size_t)blockIdx.x * blockDim.x + threadIdx.x) * 4;
    float4 q = *(const float4*)(Qorig + i);
    float sx = 0.f, sy = 0.f, sz = 0.f, sw = 0.f;
#pragma unroll
    for (int z = 0; z < KSPLIT; z++) {
        float4 p = *(const float4*)(g_part + (size_t)z * NB * D_DIM + i);
        sx += p.x; sy += p.y; sz += p.z; sw += p.w;
    }
    float4 o;
    o.x = fmaf(ALPHA, sx, q.x);
    o.y = fmaf(ALPHA, sy, q.y);
    o.z = fmaf(ALPHA, sz, q.z);
    o.w = fmaf(ALPHA, sw, q.w);
    *(float4*)(Out + i) = o;
}

// ---------------------------------------------------------------------------
extern "C" void kernel_launch(void* const* d_in, const int* in_sizes, int n_in,
                              void* d_out, int out_size) {
    const float* qf;
    const float* sk;
    if (in_sizes[0] == NB * D_DIM) {
        qf = (const float*)d_in[0];
        sk = (const float*)d_in[1];
    } else {
        qf = (const float*)d_in[1];
        sk = (const float*)d_in[0];
    }

    cudaFuncSetAttribute(fused_kernel, cudaFuncAttributeMaxDynamicSharedMemorySize,
                         SMEM_TOTAL);

    norm_rows<<<NK / 8, 256>>>(sk, NK, 1);
    norm_rows<<<NB / 8, 256>>>(qf, NB, 0);

    dim3 g(NB / QT, KSPLIT);   // (64, 4)
    fused_kernel<<<g, 256, SMEM_TOTAL>>>();

    reduce_kernel<<<(NB * D_DIM) / (256 * 4), 256>>>(qf, (float*)d_out);
}